// round 6
// baseline (speedup 1.0000x reference)
#include <cuda_runtime.h>
#include <cuda_bf16.h>
#include <cstdint>

// ---------------- problem constants ----------------
#define NROWS   8192
#define DDIM    256
#define HALF_N  4096

// ---------------- tiling ----------------
#define TM      128                   // rows per CTA
#define TN      64                    // cols per B tile
#define CS      4                     // column splits -> 256 CTAs, 2 per SM
#define COLS_PER_CTA (NROWS / CS)     // 2048
#define NTILES  (COLS_PER_CTA / TN)   // 32

// fp8 rows: 256 bytes, padded stride 272B
#define ROWB    272
#define SA_BYTES (TM * ROWB)          // 34816 (A staging, used once)
#define SB_BYTES (TN * ROWB)          // 17408
#define SUMS_OFF (SA_BYTES + 2 * SB_BYTES)
#define SMEM_BYTES (SUMS_OFF + TM * 2 * (int)sizeof(float))   // ~70.7KB -> 2 CTAs/SM

// exp(2*c) = 2^(c * 2*log2(e))
#define TWO_LOG2E 2.8853900817779268f

// ---------------- device scratch ----------------
__device__ __align__(16) uint8_t g_z8[NROWS * DDIM];   // e4m3 normalized rows
__device__ float g_pos[NROWS];
__device__ float g_S[NROWS * CS];

// ---------------- helpers ----------------
__device__ __forceinline__ void cp16(void* dst_smem, const void* src_gmem) {
    uint32_t d = (uint32_t)__cvta_generic_to_shared(dst_smem);
    asm volatile("cp.async.cg.shared.global [%0], [%1], 16;" :: "r"(d), "l"(src_gmem));
}
__device__ __forceinline__ uint16_t f2e4m3x2(float lo, float hi) {
    uint16_t h;
    asm("cvt.rn.satfinite.e4m3x2.f32 %0, %1, %2;" : "=h"(h) : "f"(hi), "f"(lo));
    return h;
}

// ---------------- kernel 1: fused normalize (fp32->e4m3) + exact positives ----
__global__ __launch_bounds__(256) void k_norm_pos(const float* __restrict__ zi,
                                                  const float* __restrict__ zj) {
    int warp = threadIdx.x >> 5, lane = threadIdx.x & 31;
    int p = blockIdx.x * 8 + warp;                 // pair index 0..HALF_N-1
    const float4* si = (const float4*)(zi + (size_t)p * DDIM);
    const float4* sj = (const float4*)(zj + (size_t)p * DDIM);
    float4 a0 = si[lane * 2], a1 = si[lane * 2 + 1];
    float4 b0 = sj[lane * 2], b1 = sj[lane * 2 + 1];

    float ssi = a0.x*a0.x + a0.y*a0.y + a0.z*a0.z + a0.w*a0.w
              + a1.x*a1.x + a1.y*a1.y + a1.z*a1.z + a1.w*a1.w;
    float ssj = b0.x*b0.x + b0.y*b0.y + b0.z*b0.z + b0.w*b0.w
              + b1.x*b1.x + b1.y*b1.y + b1.z*b1.z + b1.w*b1.w;
    float dot = a0.x*b0.x + a0.y*b0.y + a0.z*b0.z + a0.w*b0.w
              + a1.x*b1.x + a1.y*b1.y + a1.z*b1.z + a1.w*b1.w;
#pragma unroll
    for (int o = 16; o; o >>= 1) {
        ssi += __shfl_xor_sync(0xffffffffu, ssi, o);
        ssj += __shfl_xor_sync(0xffffffffu, ssj, o);
        dot += __shfl_xor_sync(0xffffffffu, dot, o);
    }
    float sci = 1.0f / fmaxf(sqrtf(ssi), 1e-8f);
    float scj = 1.0f / fmaxf(sqrtf(ssj), 1e-8f);

    if (lane == 0) {
        float pos = 2.0f * dot * sci * scj;
        g_pos[p] = pos;
        g_pos[p + HALF_N] = pos;
    }

    uint16_t h0 = f2e4m3x2(a0.x * sci, a0.y * sci);
    uint16_t h1 = f2e4m3x2(a0.z * sci, a0.w * sci);
    uint16_t h2 = f2e4m3x2(a1.x * sci, a1.y * sci);
    uint16_t h3 = f2e4m3x2(a1.z * sci, a1.w * sci);
    uint2 wa = { (uint32_t)h0 | ((uint32_t)h1 << 16),
                 (uint32_t)h2 | ((uint32_t)h3 << 16) };
    reinterpret_cast<uint2*>(g_z8 + (size_t)p * DDIM)[lane] = wa;

    h0 = f2e4m3x2(b0.x * scj, b0.y * scj);
    h1 = f2e4m3x2(b0.z * scj, b0.w * scj);
    h2 = f2e4m3x2(b1.x * scj, b1.y * scj);
    h3 = f2e4m3x2(b1.z * scj, b1.w * scj);
    uint2 wb = { (uint32_t)h0 | ((uint32_t)h1 << 16),
                 (uint32_t)h2 | ((uint32_t)h3 << 16) };
    reinterpret_cast<uint2*>(g_z8 + (size_t)(p + HALF_N) * DDIM)[lane] = wb;
}

// ---------------- kernel 2: fp8 GEMM (A in registers) + sum-exp ----------------
__global__ __launch_bounds__(256, 2) void k_gemm_lse() {
    extern __shared__ char smem[];
    uint8_t* sA  = (uint8_t*)smem;
    uint8_t* sB0 = (uint8_t*)(smem + SA_BYTES);
    uint8_t* sB1 = (uint8_t*)(smem + SA_BYTES + SB_BYTES);
    float* sums = (float*)(smem + SUMS_OFF);

    int tid = threadIdx.x;
    int lane = tid & 31, warp = tid >> 5;
    int wm = warp >> 1, wn = warp & 1;           // 4x2 warp grid, warp tile 32x32
    int cs = blockIdx.x, rt = blockIdx.y;
    int row0 = rt * TM, colBase = cs * COLS_PER_CTA;

    // stage A panel (128 rows x 256B): 8 chunks per thread
#pragma unroll
    for (int i = 0; i < 8; i++) {
        int id = i * 256 + tid;
        int rowl = id >> 4, ch = id & 15;
        cp16(sA + rowl * ROWB + ch * 16,
             g_z8 + (size_t)(row0 + rowl) * DDIM + ch * 16);
    }
    // stage B tile 0: 4 chunks per thread
#pragma unroll
    for (int i = 0; i < 4; i++) {
        int id = i * 256 + tid;
        int rowl = id >> 4, ch = id & 15;
        cp16(sB0 + rowl * ROWB + ch * 16,
             g_z8 + (size_t)(colBase + rowl) * DDIM + ch * 16);
    }
    asm volatile("cp.async.commit_group;");
    asm volatile("cp.async.wait_group 0;");
    __syncthreads();

    uint32_t sA32 = (uint32_t)__cvta_generic_to_shared(sA);
    uint32_t sB32[2] = {(uint32_t)__cvta_generic_to_shared(sB0),
                        (uint32_t)__cvta_generic_to_shared(sB1)};

    // hoist ALL A fragments into registers: a[mt][ks][4], 64 regs/thread
    uint32_t a[2][8][4];
#pragma unroll
    for (int mt = 0; mt < 2; mt++) {
        uint32_t base = sA32 + (uint32_t)((wm * 32 + mt * 16 + (lane & 15)) * ROWB
                                          + (lane >> 4) * 16);
#pragma unroll
        for (int ks = 0; ks < 8; ks++) {
            asm volatile("ldmatrix.sync.aligned.m8n8.x4.shared.b16 {%0,%1,%2,%3}, [%4];"
                         : "=r"(a[mt][ks][0]), "=r"(a[mt][ks][1]),
                           "=r"(a[mt][ks][2]), "=r"(a[mt][ks][3])
                         : "r"(base + ks * 32));
        }
    }

    // B ldmatrix lane bases (pair p covers n-tiles 2p, 2p+1)
    uint32_t bOff[2];
#pragma unroll
    for (int p = 0; p < 2; p++)
        bOff[p] = (uint32_t)((wn * 32 + p * 16 + ((lane >> 4) << 3) + (lane & 7)) * ROWB
                             + ((lane >> 3) & 1) * 16);

    float rs[2][2] = {{0.f, 0.f}, {0.f, 0.f}};

    // pipeline: sync -> prefetch t+1 -> wait tile t -> compute -> epilogue
    for (int ct = 0; ct < NTILES; ct++) {
        int buf = ct & 1;
        __syncthreads();   // all warps done reading buf^1 (tile ct-1) before overwrite
        if (ct + 1 < NTILES) {
            uint8_t* dstB = buf ? sB0 : sB1;
            int gcol0 = colBase + (ct + 1) * TN;
#pragma unroll
            for (int i = 0; i < 4; i++) {
                int id = i * 256 + tid;
                int rowl = id >> 4, ch = id & 15;
                cp16(dstB + rowl * ROWB + ch * 16,
                     g_z8 + (size_t)(gcol0 + rowl) * DDIM + ch * 16);
            }
            asm volatile("cp.async.commit_group;");
            asm volatile("cp.async.wait_group 1;");   // tile ct's data has landed
        } else {
            asm volatile("cp.async.wait_group 0;");
        }

        float c[2][4][4];
#pragma unroll
        for (int mt = 0; mt < 2; mt++)
#pragma unroll
            for (int nt = 0; nt < 4; nt++)
#pragma unroll
                for (int e = 0; e < 4; e++) c[mt][nt][e] = 0.f;

        uint32_t bBase = sB32[buf];
#pragma unroll
        for (int ks = 0; ks < 8; ks++) {
            uint32_t b[4][2];
#pragma unroll
            for (int p = 0; p < 2; p++) {
                uint32_t addr = bBase + bOff[p] + ks * 32;
                asm volatile("ldmatrix.sync.aligned.m8n8.x4.shared.b16 {%0,%1,%2,%3}, [%4];"
                             : "=r"(b[2*p][0]), "=r"(b[2*p][1]),
                               "=r"(b[2*p+1][0]), "=r"(b[2*p+1][1])
                             : "r"(addr));
            }
#pragma unroll
            for (int mt = 0; mt < 2; mt++)
#pragma unroll
                for (int nt = 0; nt < 4; nt++)
                    asm volatile("mma.sync.aligned.m16n8k32.row.col.f32.e4m3.e4m3.f32 "
                                 "{%0,%1,%2,%3}, {%4,%5,%6,%7}, {%8,%9}, {%0,%1,%2,%3};"
                                 : "+f"(c[mt][nt][0]), "+f"(c[mt][nt][1]),
                                   "+f"(c[mt][nt][2]), "+f"(c[mt][nt][3])
                                 : "r"(a[mt][ks][0]), "r"(a[mt][ks][1]),
                                   "r"(a[mt][ks][2]), "r"(a[mt][ks][3]),
                                   "r"(b[nt][0]), "r"(b[nt][1]));
        }

        // epilogue: exp, diagonal mask, row accumulate (pos exact elsewhere)
        int gcol0 = colBase + ct * TN;
#pragma unroll
        for (int mt = 0; mt < 2; mt++) {
#pragma unroll
            for (int hi = 0; hi < 2; hi++) {
                int i = row0 + wm * 32 + mt * 16 + (lane >> 2) + hi * 8;
                float acc = 0.f;
#pragma unroll
                for (int nt = 0; nt < 4; nt++) {
#pragma unroll
                    for (int lo = 0; lo < 2; lo++) {
                        float cv = c[mt][nt][hi * 2 + lo];
                        int j = gcol0 + wn * 32 + nt * 8 + ((lane & 3) << 1) + lo;
                        float ev;
                        asm("ex2.approx.f32 %0, %1;" : "=f"(ev) : "f"(cv * TWO_LOG2E));
                        if (j == i) ev = 0.f;
                        acc += ev;
                    }
                }
                rs[mt][hi] += acc;
            }
        }
    }

    // reduce per-row sums: quad shuffle, then combine the two wn warps via smem
#pragma unroll
    for (int mt = 0; mt < 2; mt++)
#pragma unroll
        for (int hi = 0; hi < 2; hi++) {
            float v = rs[mt][hi];
            v += __shfl_xor_sync(0xffffffffu, v, 1);
            v += __shfl_xor_sync(0xffffffffu, v, 2);
            if ((lane & 3) == 0) {
                int rl = wm * 32 + mt * 16 + (lane >> 2) + hi * 8;
                sums[rl * 2 + wn] = v;
            }
        }
    __syncthreads();
    if (tid < TM) {
        float S = sums[tid * 2] + sums[tid * 2 + 1];
        g_S[(size_t)(row0 + tid) * CS + cs] = S;
    }
}

// ---------------- kernel 3: deterministic final reduction ----------------
__global__ __launch_bounds__(256) void k_finalize(float* __restrict__ out) {
    __shared__ float red[256];
    int tid = threadIdx.x;
    float acc = 0.f;
    for (int r = tid; r < NROWS; r += 256) {
        float S = g_S[r * CS] + g_S[r * CS + 1] + g_S[r * CS + 2] + g_S[r * CS + 3];
        acc += logf(S) - g_pos[r];
    }
    red[tid] = acc;
    __syncthreads();
#pragma unroll
    for (int s = 128; s > 0; s >>= 1) {
        if (tid < s) red[tid] += red[tid + s];
        __syncthreads();
    }
    if (tid == 0) out[0] = red[0] * (1.0f / (float)NROWS);
}

// ---------------- launcher ----------------
extern "C" void kernel_launch(void* const* d_in, const int* in_sizes, int n_in,
                              void* d_out, int out_size) {
    (void)in_sizes; (void)n_in; (void)out_size;
    const float* zi = (const float*)d_in[0];
    const float* zj = (const float*)d_in[1];
    float* out = (float*)d_out;

    cudaFuncSetAttribute((const void*)k_gemm_lse,
                         cudaFuncAttributeMaxDynamicSharedMemorySize, SMEM_BYTES);

    k_norm_pos<<<HALF_N / 8, 256>>>(zi, zj);
    k_gemm_lse<<<dim3(CS, NROWS / TM), 256, SMEM_BYTES>>>();
    k_finalize<<<1, 256>>>(out);
}

// round 8
// speedup vs baseline: 2.0532x; 2.0532x over previous
#include <cuda_runtime.h>
#include <cuda_bf16.h>
#include <cstdint>

// ---------------- problem constants ----------------
#define NROWS   8192
#define DDIM    256
#define HALF_N  4096

// ---------------- tiling: symmetric upper-triangle blocks ----------------
#define BLK     128                   // block size (rows and cols)
#define NT      (NROWS / BLK)         // 64 tiles
#define NPAIRS  (NT * (NT + 1) / 2)   // 2080 CTAs

#define ROWB    272                   // padded fp8 row stride (256B data)
#define SP_BYTES (BLK * ROWB)         // 34816 per panel
#define SROW_OFF (2 * SP_BYTES)                    // [128][2] floats
#define SCOL_OFF (SROW_OFF + BLK * 2 * 4)          // [128][4] floats
#define SMEM_BYTES (SCOL_OFF + BLK * 4 * 4)        // 72704 B -> 2 CTAs/SM

// exp(2*c) = 2^(c * 2*log2(e))
#define TWO_LOG2E 2.8853900817779268f

// ---------------- device scratch ----------------
__device__ __align__(16) uint8_t g_z8[NROWS * DDIM];   // e4m3 normalized rows
__device__ float g_pos[NROWS];
__device__ float g_part[NT][NROWS];    // slot-major partial sums (2MB)
__device__ float g_row[NROWS];

// ---------------- helpers ----------------
__device__ __forceinline__ void cp16(void* dst_smem, const void* src_gmem) {
    uint32_t d = (uint32_t)__cvta_generic_to_shared(dst_smem);
    asm volatile("cp.async.cg.shared.global [%0], [%1], 16;" :: "r"(d), "l"(src_gmem));
}
__device__ __forceinline__ uint16_t f2e4m3x2(float lo, float hi) {
    uint16_t h;
    asm("cvt.rn.satfinite.e4m3x2.f32 %0, %1, %2;" : "=h"(h) : "f"(hi), "f"(lo));
    return h;
}

// ---------------- kernel 1: fused normalize (fp32->e4m3) + exact positives ----
__global__ __launch_bounds__(256) void k_norm_pos(const float* __restrict__ zi,
                                                  const float* __restrict__ zj) {
    int warp = threadIdx.x >> 5, lane = threadIdx.x & 31;
    int p = blockIdx.x * 8 + warp;                 // pair index 0..HALF_N-1
    const float4* si = (const float4*)(zi + (size_t)p * DDIM);
    const float4* sj = (const float4*)(zj + (size_t)p * DDIM);
    float4 a0 = si[lane * 2], a1 = si[lane * 2 + 1];
    float4 b0 = sj[lane * 2], b1 = sj[lane * 2 + 1];

    float ssi = a0.x*a0.x + a0.y*a0.y + a0.z*a0.z + a0.w*a0.w
              + a1.x*a1.x + a1.y*a1.y + a1.z*a1.z + a1.w*a1.w;
    float ssj = b0.x*b0.x + b0.y*b0.y + b0.z*b0.z + b0.w*b0.w
              + b1.x*b1.x + b1.y*b1.y + b1.z*b1.z + b1.w*b1.w;
    float dot = a0.x*b0.x + a0.y*b0.y + a0.z*b0.z + a0.w*b0.w
              + a1.x*b1.x + a1.y*b1.y + a1.z*b1.z + a1.w*b1.w;
#pragma unroll
    for (int o = 16; o; o >>= 1) {
        ssi += __shfl_xor_sync(0xffffffffu, ssi, o);
        ssj += __shfl_xor_sync(0xffffffffu, ssj, o);
        dot += __shfl_xor_sync(0xffffffffu, dot, o);
    }
    float sci = 1.0f / fmaxf(sqrtf(ssi), 1e-8f);
    float scj = 1.0f / fmaxf(sqrtf(ssj), 1e-8f);

    if (lane == 0) {
        float pos = 2.0f * dot * sci * scj;
        g_pos[p] = pos;
        g_pos[p + HALF_N] = pos;
    }

    uint16_t h0 = f2e4m3x2(a0.x * sci, a0.y * sci);
    uint16_t h1 = f2e4m3x2(a0.z * sci, a0.w * sci);
    uint16_t h2 = f2e4m3x2(a1.x * sci, a1.y * sci);
    uint16_t h3 = f2e4m3x2(a1.z * sci, a1.w * sci);
    uint2 wa = { (uint32_t)h0 | ((uint32_t)h1 << 16),
                 (uint32_t)h2 | ((uint32_t)h3 << 16) };
    reinterpret_cast<uint2*>(g_z8 + (size_t)p * DDIM)[lane] = wa;

    h0 = f2e4m3x2(b0.x * scj, b0.y * scj);
    h1 = f2e4m3x2(b0.z * scj, b0.w * scj);
    h2 = f2e4m3x2(b1.x * scj, b1.y * scj);
    h3 = f2e4m3x2(b1.z * scj, b1.w * scj);
    uint2 wb = { (uint32_t)h0 | ((uint32_t)h1 << 16),
                 (uint32_t)h2 | ((uint32_t)h3 << 16) };
    reinterpret_cast<uint2*>(g_z8 + (size_t)(p + HALF_N) * DDIM)[lane] = wb;
}

// ---------------- kernel 2: symmetric fp8 block GEMM + dual-sided exp sums ----
__global__ __launch_bounds__(256, 2) void k_gemm_sym() {
    extern __shared__ char smem[];
    uint8_t* sA = (uint8_t*)smem;
    uint8_t* sB = (uint8_t*)(smem + SP_BYTES);
    float* srow = (float*)(smem + SROW_OFF);   // [128][2]
    float* scol = (float*)(smem + SCOL_OFF);   // [128][4]

    // decode upper-triangle pair (ti <= tj)
    int b = blockIdx.x, ti = 0, len = NT;
    while (b >= len) { b -= len; len--; ti++; }
    int tj = ti + b;
    bool diag = (ti == tj);

    int tid = threadIdx.x;
    int lane = tid & 31, warp = tid >> 5;
    int wm = warp >> 1, wn = warp & 1;         // 4x2 warp grid; warp tile 32x64
    int row0 = ti * BLK, col0 = tj * BLK;

    // stage A (rows of ti) and B (rows of tj): 8 x 16B chunks per thread each
#pragma unroll
    for (int i = 0; i < 8; i++) {
        int id = i * 256 + tid;
        int rowl = id >> 4, ch = id & 15;
        cp16(sA + rowl * ROWB + ch * 16,
             g_z8 + (size_t)(row0 + rowl) * DDIM + ch * 16);
    }
#pragma unroll
    for (int i = 0; i < 8; i++) {
        int id = i * 256 + tid;
        int rowl = id >> 4, ch = id & 15;
        cp16(sB + rowl * ROWB + ch * 16,
             g_z8 + (size_t)(col0 + rowl) * DDIM + ch * 16);
    }
    asm volatile("cp.async.commit_group;");
    asm volatile("cp.async.wait_group 0;");
    __syncthreads();

    uint32_t sA32 = (uint32_t)__cvta_generic_to_shared(sA);
    uint32_t sB32 = (uint32_t)__cvta_generic_to_shared(sB);

    uint32_t aAddr[2];
#pragma unroll
    for (int mt = 0; mt < 2; mt++)
        aAddr[mt] = sA32 + (uint32_t)((wm * 32 + mt * 16 + (lane & 15)) * ROWB
                                      + (lane >> 4) * 16);
    uint32_t bOff[4];
#pragma unroll
    for (int p = 0; p < 4; p++)
        bOff[p] = sB32 + (uint32_t)((wn * 64 + p * 16 + ((lane >> 4) << 3) + (lane & 7)) * ROWB
                                    + ((lane >> 3) & 1) * 16);

    float c[2][8][4];
#pragma unroll
    for (int mt = 0; mt < 2; mt++)
#pragma unroll
        for (int nt = 0; nt < 8; nt++)
#pragma unroll
            for (int e = 0; e < 4; e++) c[mt][nt][e] = 0.f;

    // full K=256 in 8 k-steps of 32 fp8
#pragma unroll
    for (int ks = 0; ks < 8; ks++) {
        uint32_t a[2][4];
#pragma unroll
        for (int mt = 0; mt < 2; mt++)
            asm volatile("ldmatrix.sync.aligned.m8n8.x4.shared.b16 {%0,%1,%2,%3}, [%4];"
                         : "=r"(a[mt][0]), "=r"(a[mt][1]), "=r"(a[mt][2]), "=r"(a[mt][3])
                         : "r"(aAddr[mt] + ks * 32));
        uint32_t bb[8][2];
#pragma unroll
        for (int p = 0; p < 4; p++)
            asm volatile("ldmatrix.sync.aligned.m8n8.x4.shared.b16 {%0,%1,%2,%3}, [%4];"
                         : "=r"(bb[2*p][0]), "=r"(bb[2*p][1]),
                           "=r"(bb[2*p+1][0]), "=r"(bb[2*p+1][1])
                         : "r"(bOff[p] + ks * 32));
#pragma unroll
        for (int mt = 0; mt < 2; mt++)
#pragma unroll
            for (int nt = 0; nt < 8; nt++)
                asm volatile("mma.sync.aligned.m16n8k32.row.col.f32.e4m3.e4m3.f32 "
                             "{%0,%1,%2,%3}, {%4,%5,%6,%7}, {%8,%9}, {%0,%1,%2,%3};"
                             : "+f"(c[mt][nt][0]), "+f"(c[mt][nt][1]),
                               "+f"(c[mt][nt][2]), "+f"(c[mt][nt][3])
                             : "r"(a[mt][0]), "r"(a[mt][1]), "r"(a[mt][2]), "r"(a[mt][3]),
                               "r"(bb[nt][0]), "r"(bb[nt][1]));
    }

    // epilogue: exp once, accumulate into row sums (rows of ti) AND col sums (rows of tj)
    float rs[2][2] = {{0.f, 0.f}, {0.f, 0.f}};
    float cs[8][2];
#pragma unroll
    for (int nt = 0; nt < 8; nt++) { cs[nt][0] = 0.f; cs[nt][1] = 0.f; }

#pragma unroll
    for (int mt = 0; mt < 2; mt++)
#pragma unroll
        for (int hi = 0; hi < 2; hi++) {
            int i = row0 + wm * 32 + mt * 16 + (lane >> 2) + hi * 8;
#pragma unroll
            for (int nt = 0; nt < 8; nt++)
#pragma unroll
                for (int lo = 0; lo < 2; lo++) {
                    float cv = c[mt][nt][hi * 2 + lo];
                    int j = col0 + wn * 64 + nt * 8 + ((lane & 3) << 1) + lo;
                    float ev;
                    asm("ex2.approx.f32 %0, %1;" : "=f"(ev) : "f"(cv * TWO_LOG2E));
                    if (diag && j == i) ev = 0.f;
                    rs[mt][hi] += ev;
                    cs[nt][lo] += ev;
                }
        }

    // row reduce: over lane&3 (quad), then combine wn halves via smem
#pragma unroll
    for (int mt = 0; mt < 2; mt++)
#pragma unroll
        for (int hi = 0; hi < 2; hi++) {
            float v = rs[mt][hi];
            v += __shfl_xor_sync(0xffffffffu, v, 1);
            v += __shfl_xor_sync(0xffffffffu, v, 2);
            if ((lane & 3) == 0)
                srow[(wm * 32 + mt * 16 + (lane >> 2) + hi * 8) * 2 + wn] = v;
        }
    // col reduce: over lane>>2 (8 threads), then combine wm quarters via smem
#pragma unroll
    for (int nt = 0; nt < 8; nt++)
#pragma unroll
        for (int lo = 0; lo < 2; lo++) {
            float v = cs[nt][lo];
            v += __shfl_xor_sync(0xffffffffu, v, 4);
            v += __shfl_xor_sync(0xffffffffu, v, 8);
            v += __shfl_xor_sync(0xffffffffu, v, 16);
            if (lane < 4)
                scol[(wn * 64 + nt * 8 + (lane & 3) * 2 + lo) * 4 + wm] = v;
        }
    __syncthreads();

    if (tid < BLK) {
        float rv = srow[tid * 2] + srow[tid * 2 + 1];
        g_part[tj][row0 + tid] = rv;                       // slot tj for rows of ti
        if (!diag) {
            float cv = scol[tid * 4] + scol[tid * 4 + 1]
                     + scol[tid * 4 + 2] + scol[tid * 4 + 3];
            g_part[ti][col0 + tid] = cv;                   // slot ti for rows of tj
        }
    }
}

// ---------------- kernel 3: per-row lse partial ----------------
__global__ __launch_bounds__(256) void k_rowlse() {
    int r = blockIdx.x * 256 + threadIdx.x;
    float S = 0.f;
#pragma unroll
    for (int s = 0; s < NT; s++) S += g_part[s][r];
    g_row[r] = logf(S) - g_pos[r];
}

// ---------------- kernel 4: deterministic final reduction ----------------
__global__ __launch_bounds__(256) void k_finalize(float* __restrict__ out) {
    __shared__ float red[256];
    int tid = threadIdx.x;
    float acc = 0.f;
    for (int r = tid; r < NROWS; r += 256) acc += g_row[r];
    red[tid] = acc;
    __syncthreads();
#pragma unroll
    for (int s = 128; s > 0; s >>= 1) {
        if (tid < s) red[tid] += red[tid + s];
        __syncthreads();
    }
    if (tid == 0) out[0] = red[0] * (1.0f / (float)NROWS);
}

// ---------------- launcher ----------------
extern "C" void kernel_launch(void* const* d_in, const int* in_sizes, int n_in,
                              void* d_out, int out_size) {
    (void)in_sizes; (void)n_in; (void)out_size;
    const float* zi = (const float*)d_in[0];
    const float* zj = (const float*)d_in[1];
    float* out = (float*)d_out;

    cudaFuncSetAttribute((const void*)k_gemm_sym,
                         cudaFuncAttributeMaxDynamicSharedMemorySize, SMEM_BYTES);

    k_norm_pos<<<HALF_N / 8, 256>>>(zi, zj);
    k_gemm_sym<<<NPAIRS, 256, SMEM_BYTES>>>();
    k_rowlse<<<NROWS / 256, 256>>>();
    k_finalize<<<1, 256>>>(out);
}

// round 9
// speedup vs baseline: 2.0927x; 1.0192x over previous
#include <cuda_runtime.h>
#include <cuda_bf16.h>
#include <cstdint>

// ---------------- problem constants ----------------
#define NROWS   8192
#define DDIM    256
#define HALF_N  4096

// ---------------- tiling: symmetric upper-triangle blocks ----------------
#define BLK     128                   // block size (rows and cols)
#define NT      (NROWS / BLK)         // 64 tiles
#define NPAIRS  (NT * (NT + 1) / 2)   // 2080 pairs
#define NCTA    296                   // persistent CTAs (148 SMs x occ 2)
#define CHUNK   (NPAIRS / NCTA)       // 7
#define EXTRAS  (NPAIRS - NCTA * CHUNK) // 8

#define ROWB    272                   // padded fp8 row stride (256B data)
#define SP_BYTES (BLK * ROWB)         // 34816 per panel
#define SROW_OFF (3 * SP_BYTES)                    // [128][2] floats
#define SCOL_OFF (SROW_OFF + BLK * 2 * 4)          // [128][4] floats
#define SMEM_BYTES (SCOL_OFF + BLK * 4 * 4)        // 107520 B -> 2 CTAs/SM

// exp(2*c) = 2^(c * 2*log2(e))
#define TWO_LOG2E 2.8853900817779268f

// ---------------- device scratch ----------------
__device__ __align__(16) uint8_t g_z8[NROWS * DDIM];   // e4m3 normalized rows
__device__ float g_pos[NROWS];
__device__ float g_part[NT][NROWS];    // slot-major partial sums (2MB)
__device__ float g_bsum[NROWS / 256];

// ---------------- helpers ----------------
__device__ __forceinline__ void cp16(void* dst_smem, const void* src_gmem) {
    uint32_t d = (uint32_t)__cvta_generic_to_shared(dst_smem);
    asm volatile("cp.async.cg.shared.global [%0], [%1], 16;" :: "r"(d), "l"(src_gmem));
}
__device__ __forceinline__ uint16_t f2e4m3x2(float lo, float hi) {
    uint16_t h;
    asm("cvt.rn.satfinite.e4m3x2.f32 %0, %1, %2;" : "=h"(h) : "f"(hi), "f"(lo));
    return h;
}

// stage a 128-row x 256B panel with all 256 threads (8 x 16B chunks each)
#define STAGE_PANEL(dst, grow0)                                            \
    _Pragma("unroll")                                                      \
    for (int i = 0; i < 8; i++) {                                          \
        int id = i * 256 + tid;                                            \
        int rowl = id >> 4, ch = id & 15;                                  \
        cp16((dst) + rowl * ROWB + ch * 16,                                \
             g_z8 + (size_t)((grow0) + rowl) * DDIM + ch * 16);            \
    }

// ---------------- kernel 1: fused normalize (fp32->e4m3) + exact positives ----
__global__ __launch_bounds__(256) void k_norm_pos(const float* __restrict__ zi,
                                                  const float* __restrict__ zj) {
    int warp = threadIdx.x >> 5, lane = threadIdx.x & 31;
    int p = blockIdx.x * 8 + warp;                 // pair index 0..HALF_N-1
    const float4* si = (const float4*)(zi + (size_t)p * DDIM);
    const float4* sj = (const float4*)(zj + (size_t)p * DDIM);
    float4 a0 = si[lane * 2], a1 = si[lane * 2 + 1];
    float4 b0 = sj[lane * 2], b1 = sj[lane * 2 + 1];

    float ssi = a0.x*a0.x + a0.y*a0.y + a0.z*a0.z + a0.w*a0.w
              + a1.x*a1.x + a1.y*a1.y + a1.z*a1.z + a1.w*a1.w;
    float ssj = b0.x*b0.x + b0.y*b0.y + b0.z*b0.z + b0.w*b0.w
              + b1.x*b1.x + b1.y*b1.y + b1.z*b1.z + b1.w*b1.w;
    float dot = a0.x*b0.x + a0.y*b0.y + a0.z*b0.z + a0.w*b0.w
              + a1.x*b1.x + a1.y*b1.y + a1.z*b1.z + a1.w*b1.w;
#pragma unroll
    for (int o = 16; o; o >>= 1) {
        ssi += __shfl_xor_sync(0xffffffffu, ssi, o);
        ssj += __shfl_xor_sync(0xffffffffu, ssj, o);
        dot += __shfl_xor_sync(0xffffffffu, dot, o);
    }
    float sci = 1.0f / fmaxf(sqrtf(ssi), 1e-8f);
    float scj = 1.0f / fmaxf(sqrtf(ssj), 1e-8f);

    if (lane == 0) {
        float pos = 2.0f * dot * sci * scj;
        g_pos[p] = pos;
        g_pos[p + HALF_N] = pos;
    }

    uint16_t h0 = f2e4m3x2(a0.x * sci, a0.y * sci);
    uint16_t h1 = f2e4m3x2(a0.z * sci, a0.w * sci);
    uint16_t h2 = f2e4m3x2(a1.x * sci, a1.y * sci);
    uint16_t h3 = f2e4m3x2(a1.z * sci, a1.w * sci);
    uint2 wa = { (uint32_t)h0 | ((uint32_t)h1 << 16),
                 (uint32_t)h2 | ((uint32_t)h3 << 16) };
    reinterpret_cast<uint2*>(g_z8 + (size_t)p * DDIM)[lane] = wa;

    h0 = f2e4m3x2(b0.x * scj, b0.y * scj);
    h1 = f2e4m3x2(b0.z * scj, b0.w * scj);
    h2 = f2e4m3x2(b1.x * scj, b1.y * scj);
    h3 = f2e4m3x2(b1.z * scj, b1.w * scj);
    uint2 wb = { (uint32_t)h0 | ((uint32_t)h1 << 16),
                 (uint32_t)h2 | ((uint32_t)h3 << 16) };
    reinterpret_cast<uint2*>(g_z8 + (size_t)(p + HALF_N) * DDIM)[lane] = wb;
}

// ---------------- kernel 2: persistent symmetric fp8 GEMM + dual-sided sums ----
__global__ __launch_bounds__(256, 2) void k_gemm_sym() {
    extern __shared__ char smem[];
    uint8_t* sA = (uint8_t*)smem;
    uint8_t* sB[2] = { (uint8_t*)(smem + SP_BYTES), (uint8_t*)(smem + 2 * SP_BYTES) };
    float* srow = (float*)(smem + SROW_OFF);   // [128][2]
    float* scol = (float*)(smem + SCOL_OFF);   // [128][4]

    int tid = threadIdx.x;
    int lane = tid & 31, warp = tid >> 5;
    int wm = warp >> 1, wn = warp & 1;         // 4x2 warp grid; warp tile 32x64

    // contiguous chunk of pairs for this CTA
    int b = blockIdx.x;
    int start = b * CHUNK + (b < EXTRAS ? b : EXTRAS);
    int count = CHUNK + (b < EXTRAS ? 1 : 0);

    // decode first pair (ti <= tj)
    int p = start, ti = 0, len = NT;
    while (p >= len) { p -= len; len--; ti++; }
    int tj = ti + p;

    uint32_t sA32 = (uint32_t)__cvta_generic_to_shared(sA);
    uint32_t sB32[2] = { (uint32_t)__cvta_generic_to_shared(sB[0]),
                         (uint32_t)__cvta_generic_to_shared(sB[1]) };

    // ldmatrix lane offsets (relative)
    uint32_t aRel[2];
#pragma unroll
    for (int mt = 0; mt < 2; mt++)
        aRel[mt] = (uint32_t)((wm * 32 + mt * 16 + (lane & 15)) * ROWB + (lane >> 4) * 16);
    uint32_t bRel[4];
#pragma unroll
    for (int q = 0; q < 4; q++)
        bRel[q] = (uint32_t)((wn * 64 + q * 16 + ((lane >> 4) << 3) + (lane & 7)) * ROWB
                             + ((lane >> 3) & 1) * 16);

    // initial loads: A(ti), B0(tj)
    STAGE_PANEL(sA, ti * BLK)
    STAGE_PANEL(sB[0], tj * BLK)
    asm volatile("cp.async.commit_group;");
    asm volatile("cp.async.wait_group 0;");
    __syncthreads();

    for (int k = 0; k < count; k++) {
        int buf = k & 1;
        bool diag = (ti == tj);
        int row0 = ti * BLK, col0 = tj * BLK;

        // next pair
        int nti = ti, ntj = tj + 1;
        if (ntj == NT) { nti = ti + 1; ntj = nti; }
        bool have_next = (k + 1 < count);
        bool sameA = (nti == ti);

        // prefetch next B while computing (same-A case only)
        if (have_next && sameA) {
            STAGE_PANEL(sB[buf ^ 1], ntj * BLK)
            asm volatile("cp.async.commit_group;");
        }

        // ---- compute 128x128x256 block ----
        float c[2][8][4];
#pragma unroll
        for (int mt = 0; mt < 2; mt++)
#pragma unroll
            for (int nt = 0; nt < 8; nt++)
#pragma unroll
                for (int e = 0; e < 4; e++) c[mt][nt][e] = 0.f;

        uint32_t bBase = sB32[buf];
#pragma unroll
        for (int ks = 0; ks < 8; ks++) {
            uint32_t a[2][4];
#pragma unroll
            for (int mt = 0; mt < 2; mt++)
                asm volatile("ldmatrix.sync.aligned.m8n8.x4.shared.b16 {%0,%1,%2,%3}, [%4];"
                             : "=r"(a[mt][0]), "=r"(a[mt][1]), "=r"(a[mt][2]), "=r"(a[mt][3])
                             : "r"(sA32 + aRel[mt] + ks * 32));
            uint32_t bb[8][2];
#pragma unroll
            for (int q = 0; q < 4; q++)
                asm volatile("ldmatrix.sync.aligned.m8n8.x4.shared.b16 {%0,%1,%2,%3}, [%4];"
                             : "=r"(bb[2*q][0]), "=r"(bb[2*q][1]),
                               "=r"(bb[2*q+1][0]), "=r"(bb[2*q+1][1])
                             : "r"(bBase + bRel[q] + ks * 32));
#pragma unroll
            for (int mt = 0; mt < 2; mt++)
#pragma unroll
                for (int nt = 0; nt < 8; nt++)
                    asm volatile("mma.sync.aligned.m16n8k32.row.col.f32.e4m3.e4m3.f32 "
                                 "{%0,%1,%2,%3}, {%4,%5,%6,%7}, {%8,%9}, {%0,%1,%2,%3};"
                                 : "+f"(c[mt][nt][0]), "+f"(c[mt][nt][1]),
                                   "+f"(c[mt][nt][2]), "+f"(c[mt][nt][3])
                                 : "r"(a[mt][0]), "r"(a[mt][1]), "r"(a[mt][2]), "r"(a[mt][3]),
                                   "r"(bb[nt][0]), "r"(bb[nt][1]));
        }

        // ---- epilogue: exp once, row sums (ti rows) + col sums (tj rows) ----
        float rs[2][2] = {{0.f, 0.f}, {0.f, 0.f}};
        float cs[8][2];
#pragma unroll
        for (int nt = 0; nt < 8; nt++) { cs[nt][0] = 0.f; cs[nt][1] = 0.f; }

#pragma unroll
        for (int mt = 0; mt < 2; mt++)
#pragma unroll
            for (int hi = 0; hi < 2; hi++) {
                int i = row0 + wm * 32 + mt * 16 + (lane >> 2) + hi * 8;
#pragma unroll
                for (int nt = 0; nt < 8; nt++)
#pragma unroll
                    for (int lo = 0; lo < 2; lo++) {
                        float cv = c[mt][nt][hi * 2 + lo];
                        int j = col0 + wn * 64 + nt * 8 + ((lane & 3) << 1) + lo;
                        float ev;
                        asm("ex2.approx.f32 %0, %1;" : "=f"(ev) : "f"(cv * TWO_LOG2E));
                        if (diag && j == i) ev = 0.f;
                        rs[mt][hi] += ev;
                        cs[nt][lo] += ev;
                    }
            }

#pragma unroll
        for (int mt = 0; mt < 2; mt++)
#pragma unroll
            for (int hi = 0; hi < 2; hi++) {
                float v = rs[mt][hi];
                v += __shfl_xor_sync(0xffffffffu, v, 1);
                v += __shfl_xor_sync(0xffffffffu, v, 2);
                if ((lane & 3) == 0)
                    srow[(wm * 32 + mt * 16 + (lane >> 2) + hi * 8) * 2 + wn] = v;
            }
#pragma unroll
        for (int nt = 0; nt < 8; nt++)
#pragma unroll
            for (int lo = 0; lo < 2; lo++) {
                float v = cs[nt][lo];
                v += __shfl_xor_sync(0xffffffffu, v, 4);
                v += __shfl_xor_sync(0xffffffffu, v, 8);
                v += __shfl_xor_sync(0xffffffffu, v, 16);
                if (lane < 4)
                    scol[(wn * 64 + nt * 8 + (lane & 3) * 2 + lo) * 4 + wm] = v;
            }
        __syncthreads();

        if (tid < BLK) {
            float rv = srow[tid * 2] + srow[tid * 2 + 1];
            g_part[tj][row0 + tid] = rv;                   // slot tj for rows of ti
            if (!diag) {
                float cv = scol[tid * 4] + scol[tid * 4 + 1]
                         + scol[tid * 4 + 2] + scol[tid * 4 + 3];
                g_part[ti][col0 + tid] = cv;               // slot ti for rows of tj
            }
        }

        if (have_next) {
            if (sameA) {
                asm volatile("cp.async.wait_group 0;");    // prefetched B(k+1) landed
            } else {
                __syncthreads();                           // compute done before sA overwrite
                STAGE_PANEL(sA, nti * BLK)
                STAGE_PANEL(sB[buf ^ 1], ntj * BLK)
                asm volatile("cp.async.commit_group;");
                asm volatile("cp.async.wait_group 0;");
            }
            __syncthreads();   // loads visible; also orders srow/scol reuse
        }
        ti = nti; tj = ntj;
    }
}

// ---------------- kernel 3: per-row lse + per-block partial sum ----------------
__global__ __launch_bounds__(256) void k_rowlse() {
    __shared__ float red[256];
    int tid = threadIdx.x;
    int r = blockIdx.x * 256 + tid;
    float S = 0.f;
#pragma unroll
    for (int s = 0; s < NT; s++) S += g_part[s][r];
    red[tid] = logf(S) - g_pos[r];
    __syncthreads();
#pragma unroll
    for (int s = 128; s > 0; s >>= 1) {
        if (tid < s) red[tid] += red[tid + s];
        __syncthreads();
    }
    if (tid == 0) g_bsum[blockIdx.x] = red[0];
}

// ---------------- kernel 4: tiny deterministic final reduction ----------------
__global__ __launch_bounds__(32) void k_finalize(float* __restrict__ out) {
    int tid = threadIdx.x;
    float v = g_bsum[tid];     // exactly 32 blocks
#pragma unroll
    for (int o = 16; o; o >>= 1) v += __shfl_xor_sync(0xffffffffu, v, o);
    if (tid == 0) out[0] = v * (1.0f / (float)NROWS);
}

// ---------------- launcher ----------------
extern "C" void kernel_launch(void* const* d_in, const int* in_sizes, int n_in,
                              void* d_out, int out_size) {
    (void)in_sizes; (void)n_in; (void)out_size;
    const float* zi = (const float*)d_in[0];
    const float* zj = (const float*)d_in[1];
    float* out = (float*)d_out;

    cudaFuncSetAttribute((const void*)k_gemm_sym,
                         cudaFuncAttributeMaxDynamicSharedMemorySize, SMEM_BYTES);

    k_norm_pos<<<HALF_N / 8, 256>>>(zi, zj);
    k_gemm_sym<<<NCTA, 256, SMEM_BYTES>>>();
    k_rowlse<<<NROWS / 256, 256>>>();
    k_finalize<<<1, 32>>>(out);
}